// round 1
// baseline (speedup 1.0000x reference)
#include <cuda_runtime.h>
#include <cuda_bf16.h>
#include <mma.h>

using namespace nvcuda;

// Scratch for Y = X @ w  (N_NODES x 128 fp32 = 51.2 MB). Static device global
// (allocation inside kernel_launch is forbidden).
#define MAX_NODES 100000
__device__ float g_Y[(size_t)MAX_NODES * 128];

// ---------------------------------------------------------------------------
// Kernel 1: out[n, :] = b[:]   (bias broadcast; atomics accumulate on top)
// ---------------------------------------------------------------------------
__global__ void init_out_kernel(float* __restrict__ out,
                                const float* __restrict__ b,
                                int total4) {
    int idx = blockIdx.x * blockDim.x + threadIdx.x;
    if (idx < total4) {
        float4 bv = reinterpret_cast<const float4*>(b)[idx & 31];
        reinterpret_cast<float4*>(out)[idx] = bv;
    }
}

// ---------------------------------------------------------------------------
// Kernel 2: Y = X @ W  via tf32 wmma (m16n16k8). Each warp computes a 32x128
// strip (2 m-tiles x 8 n-tiles), K looped 16x. W (64KB) stays L1/L2 resident.
// ---------------------------------------------------------------------------
__global__ __launch_bounds__(128)
void gemm_tf32_kernel(const float* __restrict__ X,
                      const float* __restrict__ W,
                      int n_strips) {
    int warp = (blockIdx.x * blockDim.x + threadIdx.x) >> 5;
    if (warp >= n_strips) return;
    size_t row0 = (size_t)warp * 32;

    wmma::fragment<wmma::accumulator, 16, 16, 8, float> acc0[8], acc1[8];
#pragma unroll
    for (int n = 0; n < 8; n++) {
        wmma::fill_fragment(acc0[n], 0.0f);
        wmma::fill_fragment(acc1[n], 0.0f);
    }

#pragma unroll
    for (int k = 0; k < 16; k++) {
        wmma::fragment<wmma::matrix_a, 16, 16, 8, wmma::precision::tf32,
                       wmma::row_major> a0, a1;
        wmma::load_matrix_sync(a0, X + row0 * 128 + k * 8, 128);
        wmma::load_matrix_sync(a1, X + (row0 + 16) * 128 + k * 8, 128);
#pragma unroll
        for (int i = 0; i < a0.num_elements; i++) {
            a0.x[i] = wmma::__float_to_tf32(a0.x[i]);
            a1.x[i] = wmma::__float_to_tf32(a1.x[i]);
        }
#pragma unroll
        for (int n = 0; n < 8; n++) {
            wmma::fragment<wmma::matrix_b, 16, 16, 8, wmma::precision::tf32,
                           wmma::row_major> bf;
            wmma::load_matrix_sync(bf, W + (size_t)k * 8 * 128 + n * 16, 128);
#pragma unroll
            for (int i = 0; i < bf.num_elements; i++)
                bf.x[i] = wmma::__float_to_tf32(bf.x[i]);
            wmma::mma_sync(acc0[n], a0, bf, acc0[n]);
            wmma::mma_sync(acc1[n], a1, bf, acc1[n]);
        }
    }

#pragma unroll
    for (int n = 0; n < 8; n++) {
        wmma::store_matrix_sync(g_Y + row0 * 128 + n * 16, acc0[n], 128,
                                wmma::mem_row_major);
        wmma::store_matrix_sync(g_Y + (row0 + 16) * 128 + n * 16, acc1[n], 128,
                                wmma::mem_row_major);
    }
}

// Scalar tail for rows not covered by 32-row strips (unused at N=100000, kept
// for shape robustness).
__global__ void gemm_tail_kernel(const float* __restrict__ X,
                                 const float* __restrict__ W,
                                 int row_start, int n_rows) {
    int r = row_start + blockIdx.x;
    if ((int)blockIdx.x >= n_rows) return;
    int j = threadIdx.x;  // 128 threads = 128 output cols
    float acc = 0.0f;
#pragma unroll 8
    for (int k = 0; k < 128; k++)
        acc += X[(size_t)r * 128 + k] * W[(size_t)k * 128 + j];
    g_Y[(size_t)r * 128 + j] = acc;
}

// ---------------------------------------------------------------------------
// Kernel 3: for each edge e: out[ref_B[e], :] += Y[ref_A[e], :]
// One warp per edge: coalesced 512B gather + red.global.add.v4.f32 scatter.
// ---------------------------------------------------------------------------
__global__ __launch_bounds__(256)
void scatter_kernel(const int* __restrict__ refA,
                    const int* __restrict__ refB,
                    float* __restrict__ out, int E) {
    int w = (blockIdx.x * blockDim.x + threadIdx.x) >> 5;
    int lane = threadIdx.x & 31;
    if (w >= E) return;
    int a = __ldg(refA + w);
    int d = __ldg(refB + w);
    float4 v = reinterpret_cast<const float4*>(g_Y + (size_t)a * 128)[lane];
    float* dst = out + (size_t)d * 128 + (size_t)lane * 4;
    asm volatile("red.global.add.v4.f32 [%0], {%1,%2,%3,%4};"
                 :: "l"(dst), "f"(v.x), "f"(v.y), "f"(v.z), "f"(v.w)
                 : "memory");
}

// ---------------------------------------------------------------------------
// Launch
// ---------------------------------------------------------------------------
extern "C" void kernel_launch(void* const* d_in, const int* in_sizes, int n_in,
                              void* d_out, int out_size) {
    const float* X    = (const float*)d_in[0];
    const int*   refA = (const int*)d_in[1];
    const int*   refB = (const int*)d_in[2];
    const float* W    = (const float*)d_in[3];
    const float* b    = (const float*)d_in[4];
    float* out = (float*)d_out;

    int N = in_sizes[0] / 128;   // 100000
    int E = in_sizes[1];         // 640000

    // 1) out = b (broadcast)
    int total4 = N * 32;  // float4s
    init_out_kernel<<<(total4 + 255) / 256, 256>>>(out, b, total4);

    // 2) Y = X @ W (tf32 tensor cores)
    int n_strips = N / 32;
    int gblocks = (n_strips + 3) / 4;  // 4 warps (128 thr) per block
    gemm_tf32_kernel<<<gblocks, 128>>>(X, W, n_strips);
    int tail = N - n_strips * 32;
    if (tail > 0)
        gemm_tail_kernel<<<tail, 128>>>(X, W, n_strips * 32, tail);

    // 3) edge scatter-add into out
    long long tw = (long long)E * 32;  // one warp per edge
    scatter_kernel<<<(unsigned)((tw + 255) / 256), 256>>>(refA, refB, out, E);
}